// round 1
// baseline (speedup 1.0000x reference)
#include <cuda_runtime.h>
#include <cuda_bf16.h>
#include <math.h>

#define NN 50000
#define NE 1600000
#define DD 128
#define OO 64

// ---------------- device scratch (allocation-free rule: __device__ globals) ---------
__device__ int   g_is64;
__device__ int   g_deg[NN];
__device__ float g_dinv[NN];
__device__ float g_sinv[NN];
__device__ float g_as[NN];
__device__ float g_ad[NN];
__device__ int   g_mkey[NN];
__device__ float g_den[NN];
__device__ float g_t[(size_t)NN * DD];
__device__ float g_h[(size_t)NN * DD];
__device__ float g_agg[(size_t)NN * DD];

// ---------------- helpers ----------------
__device__ __forceinline__ int f2key(float f) {
    int i = __float_as_int(f);
    return i < 0 ? (i ^ 0x7fffffff) : i;
}
__device__ __forceinline__ float key2f(int k) {
    return __int_as_float(k < 0 ? (k ^ 0x7fffffff) : k);
}
__device__ __forceinline__ float leaky(float v) { return v > 0.f ? v : 0.2f * v; }

__device__ __forceinline__ void edge_ld(const void* ei, int e, int& s, int& d) {
    if (g_is64) {
        const long long* p = (const long long*)ei;
        s = (int)p[e]; d = (int)p[NE + e];
    } else {
        const int* p = (const int*)ei;
        s = p[e]; d = p[NE + e];
    }
}

__device__ __forceinline__ void red_add_v4(float* p, float4 v) {
    asm volatile("red.global.add.v4.f32 [%0], {%1,%2,%3,%4};"
                 :: "l"(p), "f"(v.x), "f"(v.y), "f"(v.z), "f"(v.w) : "memory");
}

// ---------------- small setup kernels ----------------
__global__ void k_detect(const long long* ei) {
    bool is64 = true;
    for (int i = 0; i < 64; i++) {
        long long v = ei[i];
        if (v < 0 || v >= NN) { is64 = false; break; }
    }
    g_is64 = is64 ? 1 : 0;
}

__global__ void k_zero_i(int* p, int n) {
    int i = blockIdx.x * blockDim.x + threadIdx.x;
    if (i < n) p[i] = 0;
}
__global__ void k_zero_f4(float4* p, int n4) {
    int i = blockIdx.x * blockDim.x + threadIdx.x;
    if (i < n4) p[i] = make_float4(0.f, 0.f, 0.f, 0.f);
}

__global__ void k_deg(const void* ei) {
    int e = blockIdx.x * blockDim.x + threadIdx.x;
    if (e >= NE) return;
    int s, d; edge_ld(ei, e, s, d);
    atomicAdd(&g_deg[d], 1);
}

__global__ void k_scal() {
    int i = blockIdx.x * blockDim.x + threadIdx.x;
    if (i >= NN) return;
    int deg = g_deg[i];
    g_dinv[i] = rsqrtf((float)(deg + 1));
    g_sinv[i] = 1.0f / (float)max(deg, 1);
}

// ---------------- GEMM: C[NN x BN] = (rowscale?) A[NN x 128] @ B[128 x BN] ----------
// BM=128, BK=16, TM=8. threads=256. BN in {128,64}, TN in {8,4}.
template<int BN, int TN, bool RS, bool ACC, bool BIAS, bool RELU>
__global__ void k_gemm(const float* __restrict__ A, const float* __restrict__ B,
                       float* __restrict__ C, const float* __restrict__ rs,
                       const float* __restrict__ bias) {
    constexpr int BM = 128, BK = 16, TM = 8;
    __shared__ float As[BK][BM];
    __shared__ float Bs[BK][BN];
    const int tid = threadIdx.x;
    const int m0 = blockIdx.x * BM;
    const int tcol = tid & 15;   // BN/TN == 16 for both configs
    const int trow = tid >> 4;

    float acc[TM][TN];
#pragma unroll
    for (int i = 0; i < TM; i++)
#pragma unroll
        for (int j = 0; j < TN; j++) acc[i][j] = 0.f;

    for (int k0 = 0; k0 < DD; k0 += BK) {
        // A tile: 128x16, 2 float4 per thread
#pragma unroll
        for (int l = 0; l < 2; l++) {
            int idx = (tid + l * 256) * 4;
            int row = idx >> 4;
            int kk = idx & 15;
            int gr = m0 + row;
            float4 v = make_float4(0.f, 0.f, 0.f, 0.f);
            float sc = 1.f;
            if (gr < NN) {
                v = *(const float4*)(A + (size_t)gr * DD + k0 + kk);
                if (RS) sc = rs[gr];
            }
            if (RS) { v.x *= sc; v.y *= sc; v.z *= sc; v.w *= sc; }
            As[kk + 0][row] = v.x;
            As[kk + 1][row] = v.y;
            As[kk + 2][row] = v.z;
            As[kk + 3][row] = v.w;
        }
        // B tile: 16 x BN
#pragma unroll
        for (int l = 0; l < (BK * BN) / 1024; l++) {
            int idx = (tid + l * 256) * 4;
            int kk = idx / BN;
            int col = idx % BN;
            *(float4*)&Bs[kk][col] = *(const float4*)(B + (size_t)(k0 + kk) * BN + col);
        }
        __syncthreads();
#pragma unroll
        for (int kk = 0; kk < BK; kk++) {
            float a[TM], b[TN];
            *(float4*)&a[0] = *(float4*)&As[kk][trow * TM];
            *(float4*)&a[4] = *(float4*)&As[kk][trow * TM + 4];
            *(float4*)&b[0] = *(float4*)&Bs[kk][tcol * TN];
            if (TN == 8) *(float4*)&b[4] = *(float4*)&Bs[kk][tcol * TN + 4];
#pragma unroll
            for (int i = 0; i < TM; i++)
#pragma unroll
                for (int j = 0; j < TN; j++) acc[i][j] = fmaf(a[i], b[j], acc[i][j]);
        }
        __syncthreads();
    }
#pragma unroll
    for (int i = 0; i < TM; i++) {
        int gr = m0 + trow * TM + i;
        if (gr >= NN) break;
#pragma unroll
        for (int j = 0; j < TN; j += 4) {
            float4 v = *(float4*)&acc[i][j];
            int col = tcol * TN + j;
            float* cp = C + (size_t)gr * BN + col;
            if (ACC) {
                float4 o = *(const float4*)cp;
                v.x += o.x; v.y += o.y; v.z += o.z; v.w += o.w;
            }
            if (BIAS) {
                float4 bb = *(const float4*)(bias + col);
                v.x += bb.x; v.y += bb.y; v.z += bb.z; v.w += bb.w;
            }
            if (RELU) {
                v.x = fmaxf(v.x, 0.f); v.y = fmaxf(v.y, 0.f);
                v.z = fmaxf(v.z, 0.f); v.w = fmaxf(v.w, 0.f);
            }
            *(float4*)cp = v;
        }
    }
}

// ---------------- GCN aggregation (D=128) ----------------
__global__ void k_gcn_init(const float* __restrict__ t, float* __restrict__ out) {
    int i = blockIdx.x * blockDim.x + threadIdx.x;   // float4 index
    if (i >= NN * (DD / 4)) return;
    int row = i / (DD / 4);
    float c = g_dinv[row]; c *= c;
    float4 v = ((const float4*)t)[i];
    v.x *= c; v.y *= c; v.z *= c; v.w *= c;
    ((float4*)out)[i] = v;
}

__global__ void k_scatter_gcn(const void* __restrict__ ei, const float* __restrict__ t,
                              float* __restrict__ out) {
    int w = (blockIdx.x * blockDim.x + threadIdx.x) >> 5;
    int lane = threadIdx.x & 31;
    if (w >= NE) return;
    int s, d; edge_ld(ei, w, s, d);
    float c = g_dinv[s] * g_dinv[d];
    float4 v = *(const float4*)(t + (size_t)s * DD + lane * 4);
    v.x *= c; v.y *= c; v.z *= c; v.w *= c;
    red_add_v4(out + (size_t)d * DD + lane * 4, v);
}

__global__ void k_scatter_sum(const void* __restrict__ ei, const float* __restrict__ t,
                              float* __restrict__ out) {
    int w = (blockIdx.x * blockDim.x + threadIdx.x) >> 5;
    int lane = threadIdx.x & 31;
    if (w >= NE) return;
    int s, d; edge_ld(ei, w, s, d);
    float4 v = *(const float4*)(t + (size_t)s * DD + lane * 4);
    red_add_v4(out + (size_t)d * DD + lane * 4, v);
}

__global__ void k_bias_relu(const float* __restrict__ src, float* __restrict__ dst,
                            const float* __restrict__ bias) {
    int i = blockIdx.x * blockDim.x + threadIdx.x;   // float4 index
    if (i >= NN * (DD / 4)) return;
    int c4 = i & (DD / 4 - 1);
    float4 b = ((const float4*)bias)[c4];
    float4 v = ((const float4*)src)[i];
    v.x = fmaxf(v.x + b.x, 0.f); v.y = fmaxf(v.y + b.y, 0.f);
    v.z = fmaxf(v.z + b.z, 0.f); v.w = fmaxf(v.w + b.w, 0.f);
    ((float4*)dst)[i] = v;
}

// ---------------- GAT ----------------
__global__ void k_alpha(const float* __restrict__ t, const float* __restrict__ a_s,
                        const float* __restrict__ a_d) {
    int w = (blockIdx.x * blockDim.x + threadIdx.x) >> 5;
    int lane = threadIdx.x & 31;
    if (w >= NN) return;
    float4 tv = *(const float4*)(t + (size_t)w * DD + lane * 4);
    float4 sv = *(const float4*)(a_s + lane * 4);
    float4 dv = *(const float4*)(a_d + lane * 4);
    float ss = tv.x * sv.x + tv.y * sv.y + tv.z * sv.z + tv.w * sv.w;
    float dd = tv.x * dv.x + tv.y * dv.y + tv.z * dv.z + tv.w * dv.w;
#pragma unroll
    for (int off = 16; off > 0; off >>= 1) {
        ss += __shfl_down_sync(0xffffffffu, ss, off);
        dd += __shfl_down_sync(0xffffffffu, dd, off);
    }
    if (lane == 0) {
        g_as[w] = ss;
        g_ad[w] = dd;
        g_mkey[w] = f2key(leaky(ss + dd));   // self-loop initializes the max
    }
}

__global__ void k_max_edges(const void* __restrict__ ei) {
    int e = blockIdx.x * blockDim.x + threadIdx.x;
    if (e >= NE) return;
    int s, d; edge_ld(ei, e, s, d);
    float ev = leaky(g_as[s] + g_ad[d]);
    atomicMax(&g_mkey[d], f2key(ev));
}

__global__ void k_den_init() {
    int i = blockIdx.x * blockDim.x + threadIdx.x;
    if (i >= NN) return;
    float es = leaky(g_as[i] + g_ad[i]);
    g_den[i] = expf(es - key2f(g_mkey[i]));
}

__global__ void k_den_edges(const void* __restrict__ ei) {
    int e = blockIdx.x * blockDim.x + threadIdx.x;
    if (e >= NE) return;
    int s, d; edge_ld(ei, e, s, d);
    float ev = leaky(g_as[s] + g_ad[d]);
    atomicAdd(&g_den[d], expf(ev - key2f(g_mkey[d])));
}

__global__ void k_gat_init(const float* __restrict__ t, float* __restrict__ out) {
    int i = blockIdx.x * blockDim.x + threadIdx.x;   // float4 index
    if (i >= NN * (DD / 4)) return;
    int row = i / (DD / 4);
    float es = leaky(g_as[row] + g_ad[row]);
    float coef = expf(es - key2f(g_mkey[row])) / g_den[row];
    float4 v = ((const float4*)t)[i];
    v.x *= coef; v.y *= coef; v.z *= coef; v.w *= coef;
    ((float4*)out)[i] = v;
}

__global__ void k_gat_scatter(const void* __restrict__ ei, const float* __restrict__ t,
                              float* __restrict__ out) {
    int w = (blockIdx.x * blockDim.x + threadIdx.x) >> 5;
    int lane = threadIdx.x & 31;
    if (w >= NE) return;
    int s, d; edge_ld(ei, w, s, d);
    float ev = leaky(g_as[s] + g_ad[d]);
    float wgt = expf(ev - key2f(g_mkey[d])) / g_den[d];
    float4 v = *(const float4*)(t + (size_t)s * DD + lane * 4);
    v.x *= wgt; v.y *= wgt; v.z *= wgt; v.w *= wgt;
    red_add_v4(out + (size_t)d * DD + lane * 4, v);
}

// ---------------- output GCN (OUT=64) ----------------
__global__ void k_out_init(const float* __restrict__ t, float* __restrict__ out,
                           const float* __restrict__ bo) {
    int i = blockIdx.x * blockDim.x + threadIdx.x;   // float4 index over NN*16
    if (i >= NN * (OO / 4)) return;
    int row = i / (OO / 4);
    int c4 = i & (OO / 4 - 1);
    float c = g_dinv[row]; c *= c;
    float4 b = ((const float4*)bo)[c4];
    float4 v = ((const float4*)t)[i];
    v.x = v.x * c + b.x; v.y = v.y * c + b.y;
    v.z = v.z * c + b.z; v.w = v.w * c + b.w;
    ((float4*)out)[i] = v;
}

__global__ void k_scatter_out(const void* __restrict__ ei, const float* __restrict__ t,
                              float* __restrict__ out) {
    int tid = blockIdx.x * blockDim.x + threadIdx.x;
    int e = tid >> 4;
    int part = tid & 15;       // 16 float4 chunks cover 64 floats
    if (e >= NE) return;
    int s, d; edge_ld(ei, e, s, d);
    float c = g_dinv[s] * g_dinv[d];
    float4 v = *(const float4*)(t + (size_t)s * OO + part * 4);
    v.x *= c; v.y *= c; v.z *= c; v.w *= c;
    red_add_v4(out + (size_t)d * OO + part * 4, v);
}

// ---------------- launch ----------------
extern "C" void kernel_launch(void* const* d_in, const int* in_sizes, int n_in,
                              void* d_out, int out_size) {
    const float* x  = (const float*)d_in[0];
    const void*  ei = d_in[1];
    const float* W1 = (const float*)d_in[2];
    const float* b1 = (const float*)d_in[3];
    const float* Wl = (const float*)d_in[4];
    const float* Wr = (const float*)d_in[5];
    const float* bs = (const float*)d_in[6];
    const float* Wg = (const float*)d_in[7];
    const float* a_s = (const float*)d_in[8];
    const float* a_d = (const float*)d_in[9];
    const float* bg = (const float*)d_in[10];
    const float* Wo = (const float*)d_in[11];
    const float* bo = (const float*)d_in[12];
    float* out = (float*)d_out;

    float *p_t, *p_h, *p_agg; int* p_deg;
    cudaGetSymbolAddress((void**)&p_t, g_t);
    cudaGetSymbolAddress((void**)&p_h, g_h);
    cudaGetSymbolAddress((void**)&p_agg, g_agg);
    cudaGetSymbolAddress((void**)&p_deg, g_deg);

    const int TB = 256;
    const int bN   = (NN + TB - 1) / TB;          // 196
    const int bND4 = (NN * DD / 4) / TB;          // 6250
    const int bE   = NE / TB;                     // 6250  (thread/edge)
    const int bEW  = (NE * 32) / TB;              // 200000 (warp/edge)
    const int bNW  = (NN * 32 + TB - 1) / TB;     // 6250  (warp/node)
    const int bO4  = (NN * OO / 4 + TB - 1) / TB; // 3125
    const int bE16 = (NE * 16) / TB;              // 100000
    const int gGemm = (NN + 127) / 128;           // 391

    // setup
    k_detect<<<1, 1>>>((const long long*)ei);
    k_zero_i<<<bN, TB>>>(p_deg, NN);
    k_deg<<<bE, TB>>>(ei);
    k_scal<<<bN, TB>>>();

    // ---- layer 1: GCN + relu ----
    k_gemm<128, 8, false, false, false, false><<<gGemm, TB>>>(x, W1, p_t, nullptr, nullptr);
    k_gcn_init<<<bND4, TB>>>(p_t, p_agg);
    k_scatter_gcn<<<bEW, TB>>>(ei, p_t, p_agg);
    k_bias_relu<<<bND4, TB>>>(p_agg, p_h, b1);                 // h1 in g_h

    // ---- layer 2: SAGE(mean) + relu ----
    k_zero_f4<<<bND4, TB>>>((float4*)p_agg, NN * DD / 4);
    k_scatter_sum<<<bEW, TB>>>(ei, p_h, p_agg);
    float* p_sinv; cudaGetSymbolAddress((void**)&p_sinv, g_sinv);
    k_gemm<128, 8, true,  false, false, false><<<gGemm, TB>>>(p_agg, Wl, p_t, p_sinv, nullptr);
    k_gemm<128, 8, false, true,  true,  true ><<<gGemm, TB>>>(p_h, Wr, p_t, nullptr, bs);  // h2 in g_t

    // ---- layer 3: GAT (heads=1) + relu ----
    k_gemm<128, 8, false, false, false, false><<<gGemm, TB>>>(p_t, Wg, p_agg, nullptr, nullptr); // g in g_agg
    k_alpha<<<bNW, TB>>>(p_agg, a_s, a_d);
    k_max_edges<<<bE, TB>>>(ei);
    k_den_init<<<bN, TB>>>();
    k_den_edges<<<bE, TB>>>(ei);
    k_gat_init<<<bND4, TB>>>(p_agg, p_h);
    k_gat_scatter<<<bEW, TB>>>(ei, p_agg, p_h);
    k_bias_relu<<<bND4, TB>>>(p_h, p_h, bg);                   // h3 in g_h

    // ---- layer 4: GCN output ----
    k_gemm<64, 4, false, false, false, false><<<gGemm, TB>>>(p_h, Wo, p_t, nullptr, nullptr);
    k_out_init<<<bO4, TB>>>(p_t, out, bo);
    k_scatter_out<<<bE16, TB>>>(ei, p_t, out);
}

// round 3
// speedup vs baseline: 1.8195x; 1.8195x over previous
#include <cuda_runtime.h>
#include <cuda_bf16.h>
#include <math.h>

#define NN 50000
#define NE 1600000
#define DD 128
#define OO 64

// ---------------- device scratch ----------------
__device__ int   g_is64;
__device__ int   g_deg[NN];
__device__ float g_dinv[NN];
__device__ float g_sinv[NN];
__device__ float g_as[NN];
__device__ float g_ad[NN];
__device__ int   g_rowptr[NN + 1];
__device__ int   g_cur[NN];
__device__ int   g_csr[NE];
__device__ float g_t[(size_t)NN * DD];
__device__ float g_h[(size_t)NN * DD];
__device__ float g_agg[(size_t)NN * DD];

__device__ __forceinline__ float leaky(float v) { return v > 0.f ? v : 0.2f * v; }

__device__ __forceinline__ void edge_ld(const void* ei, int e, int& s, int& d) {
    if (g_is64) {
        const long long* p = (const long long*)ei;
        s = (int)p[e]; d = (int)p[NE + e];
    } else {
        const int* p = (const int*)ei;
        s = p[e]; d = p[NE + e];
    }
}

// ---------------- setup ----------------
__global__ void k_detect(const long long* ei) {
    bool is64 = true;
    for (int i = 0; i < 64; i++) {
        long long v = ei[i];
        if (v < 0 || v >= NN) { is64 = false; break; }
    }
    g_is64 = is64 ? 1 : 0;
}

__global__ void k_zero_i(int* p, int n) {
    int i = blockIdx.x * blockDim.x + threadIdx.x;
    if (i < n) p[i] = 0;
}

__global__ void k_deg(const void* ei) {
    int e = blockIdx.x * blockDim.x + threadIdx.x;
    if (e >= NE) return;
    int s, d; edge_ld(ei, e, s, d);
    atomicAdd(&g_deg[d], 1);
}

__global__ void k_scal() {
    int i = blockIdx.x * blockDim.x + threadIdx.x;
    if (i >= NN) return;
    int deg = g_deg[i];
    g_dinv[i] = rsqrtf((float)(deg + 1));
    g_sinv[i] = 1.0f / (float)max(deg, 1);
}

// single-block exclusive scan of g_deg -> g_rowptr, also init g_cur
__global__ void __launch_bounds__(1024) k_scan() {
    __shared__ int sh[1024];
    __shared__ int sh_carry;
    int tid = threadIdx.x;
    if (tid == 0) { sh_carry = 0; g_rowptr[0] = 0; }
    __syncthreads();
    for (int base = 0; base < NN; base += 1024) {
        int i = base + tid;
        int v = (i < NN) ? g_deg[i] : 0;
        sh[tid] = v;
        __syncthreads();
#pragma unroll
        for (int off = 1; off < 1024; off <<= 1) {
            int t = (tid >= off) ? sh[tid - off] : 0;
            __syncthreads();
            sh[tid] += t;
            __syncthreads();
        }
        int carry = sh_carry;
        if (i < NN) {
            int excl = carry + sh[tid] - v;
            g_rowptr[i + 1] = carry + sh[tid];
            g_cur[i] = excl;
        }
        __syncthreads();
        if (tid == 0) sh_carry = carry + sh[1023];
        __syncthreads();
    }
}

__global__ void k_fill(const void* ei) {
    int e = blockIdx.x * blockDim.x + threadIdx.x;
    if (e >= NE) return;
    int s, d; edge_ld(ei, e, s, d);
    int pos = atomicAdd(&g_cur[d], 1);
    g_csr[pos] = s;
}

// ---------------- GEMM: C[NN x BN] = A[NN x 128] @ B[128 x BN] ----------------
template<int BN, int TN, bool BIAS, bool RELU>
__global__ void k_gemm(const float* __restrict__ A, const float* __restrict__ B,
                       float* __restrict__ C, const float* __restrict__ bias) {
    constexpr int BM = 128, BK = 16, TM = 8;
    __shared__ float As[BK][BM];
    __shared__ float Bs[BK][BN];
    const int tid = threadIdx.x;
    const int m0 = blockIdx.x * BM;
    const int tcol = tid & 15;
    const int trow = tid >> 4;

    float acc[TM][TN];
#pragma unroll
    for (int i = 0; i < TM; i++)
#pragma unroll
        for (int j = 0; j < TN; j++) acc[i][j] = 0.f;

    for (int k0 = 0; k0 < DD; k0 += BK) {
#pragma unroll
        for (int l = 0; l < 2; l++) {
            int idx = (tid + l * 256) * 4;
            int row = idx >> 4;
            int kk = idx & 15;
            int gr = m0 + row;
            float4 v = make_float4(0.f, 0.f, 0.f, 0.f);
            if (gr < NN) v = *(const float4*)(A + (size_t)gr * DD + k0 + kk);
            As[kk + 0][row] = v.x; As[kk + 1][row] = v.y;
            As[kk + 2][row] = v.z; As[kk + 3][row] = v.w;
        }
#pragma unroll
        for (int l = 0; l < (BK * BN) / 1024; l++) {
            int idx = (tid + l * 256) * 4;
            int kk = idx / BN;
            int col = idx % BN;
            *(float4*)&Bs[kk][col] = *(const float4*)(B + (size_t)(k0 + kk) * BN + col);
        }
        __syncthreads();
#pragma unroll
        for (int kk = 0; kk < BK; kk++) {
            float a[TM], b[TN];
            *(float4*)&a[0] = *(float4*)&As[kk][trow * TM];
            *(float4*)&a[4] = *(float4*)&As[kk][trow * TM + 4];
            *(float4*)&b[0] = *(float4*)&Bs[kk][tcol * TN];
            if (TN == 8) *(float4*)&b[4] = *(float4*)&Bs[kk][tcol * TN + 4];
#pragma unroll
            for (int i = 0; i < TM; i++)
#pragma unroll
                for (int j = 0; j < TN; j++) acc[i][j] = fmaf(a[i], b[j], acc[i][j]);
        }
        __syncthreads();
    }
#pragma unroll
    for (int i = 0; i < TM; i++) {
        int gr = m0 + trow * TM + i;
        if (gr >= NN) break;
#pragma unroll
        for (int j = 0; j < TN; j += 4) {
            float4 v = *(float4*)&acc[i][j];
            int col = tcol * TN + j;
            if (BIAS) {
                float4 bb = *(const float4*)(bias + col);
                v.x += bb.x; v.y += bb.y; v.z += bb.z; v.w += bb.w;
            }
            if (RELU) {
                v.x = fmaxf(v.x, 0.f); v.y = fmaxf(v.y, 0.f);
                v.z = fmaxf(v.z, 0.f); v.w = fmaxf(v.w, 0.f);
            }
            *(float4*)(C + (size_t)gr * BN + col) = v;
        }
    }
}

// SAGE fused GEMM: C = A1@B1 + A2@B2 + bias, relu. BN=128.
__global__ void k_gemm_sage(const float* __restrict__ A1, const float* __restrict__ B1,
                            const float* __restrict__ A2, const float* __restrict__ B2,
                            float* __restrict__ C, const float* __restrict__ bias) {
    constexpr int BM = 128, BN = 128, BK = 16, TM = 8, TN = 8;
    __shared__ float As[BK][BM];
    __shared__ float Bs[BK][BN];
    const int tid = threadIdx.x;
    const int m0 = blockIdx.x * BM;
    const int tcol = tid & 15;
    const int trow = tid >> 4;

    float acc[TM][TN];
#pragma unroll
    for (int i = 0; i < TM; i++)
#pragma unroll
        for (int j = 0; j < TN; j++) acc[i][j] = 0.f;

    for (int ph = 0; ph < 2; ph++) {
        const float* A = ph ? A2 : A1;
        const float* B = ph ? B2 : B1;
        for (int k0 = 0; k0 < DD; k0 += BK) {
#pragma unroll
            for (int l = 0; l < 2; l++) {
                int idx = (tid + l * 256) * 4;
                int row = idx >> 4;
                int kk = idx & 15;
                int gr = m0 + row;
                float4 v = make_float4(0.f, 0.f, 0.f, 0.f);
                if (gr < NN) v = *(const float4*)(A + (size_t)gr * DD + k0 + kk);
                As[kk + 0][row] = v.x; As[kk + 1][row] = v.y;
                As[kk + 2][row] = v.z; As[kk + 3][row] = v.w;
            }
#pragma unroll
            for (int l = 0; l < 2; l++) {
                int idx = (tid + l * 256) * 4;
                int kk = idx / BN;
                int col = idx % BN;
                *(float4*)&Bs[kk][col] = *(const float4*)(B + (size_t)(k0 + kk) * BN + col);
            }
            __syncthreads();
#pragma unroll
            for (int kk = 0; kk < BK; kk++) {
                float a[TM], b[TN];
                *(float4*)&a[0] = *(float4*)&As[kk][trow * TM];
                *(float4*)&a[4] = *(float4*)&As[kk][trow * TM + 4];
                *(float4*)&b[0] = *(float4*)&Bs[kk][tcol * TN];
                *(float4*)&b[4] = *(float4*)&Bs[kk][tcol * TN + 4];
#pragma unroll
                for (int i = 0; i < TM; i++)
#pragma unroll
                    for (int j = 0; j < TN; j++) acc[i][j] = fmaf(a[i], b[j], acc[i][j]);
            }
            __syncthreads();
        }
    }
#pragma unroll
    for (int i = 0; i < TM; i++) {
        int gr = m0 + trow * TM + i;
        if (gr >= NN) break;
#pragma unroll
        for (int j = 0; j < TN; j += 4) {
            float4 v = *(float4*)&acc[i][j];
            int col = tcol * TN + j;
            float4 bb = *(const float4*)(bias + col);
            v.x = fmaxf(v.x + bb.x, 0.f); v.y = fmaxf(v.y + bb.y, 0.f);
            v.z = fmaxf(v.z + bb.z, 0.f); v.w = fmaxf(v.w + bb.w, 0.f);
            *(float4*)(C + (size_t)gr * BN + col) = v;
        }
    }
}

// ---------------- CSR gather kernels (warp per node) ----------------
// GCN layer 1: out = relu(b + dinv[d]^2*t[d] + sum_s dinv[s]dinv[d]*t[s])
__global__ void k_gcn_gather(const float* __restrict__ t, float* __restrict__ out,
                             const float* __restrict__ bias) {
    int w = (blockIdx.x * blockDim.x + threadIdx.x) >> 5;
    int lane = threadIdx.x & 31;
    if (w >= NN) return;
    float di = g_dinv[w];
    int start = g_rowptr[w], end = g_rowptr[w + 1];
    float4 acc = *(const float4*)(t + (size_t)w * DD + lane * 4);
    float cs = di * di;
    acc.x *= cs; acc.y *= cs; acc.z *= cs; acc.w *= cs;
    for (int j = start; j < end; j++) {
        int s = g_csr[j];
        float c = g_dinv[s] * di;
        float4 v = *(const float4*)(t + (size_t)s * DD + lane * 4);
        acc.x = fmaf(c, v.x, acc.x); acc.y = fmaf(c, v.y, acc.y);
        acc.z = fmaf(c, v.z, acc.z); acc.w = fmaf(c, v.w, acc.w);
    }
    float4 b = ((const float4*)bias)[lane];
    acc.x = fmaxf(acc.x + b.x, 0.f); acc.y = fmaxf(acc.y + b.y, 0.f);
    acc.z = fmaxf(acc.z + b.z, 0.f); acc.w = fmaxf(acc.w + b.w, 0.f);
    *(float4*)(out + (size_t)w * DD + lane * 4) = acc;
}

// SAGE mean aggregation: out[d] = (1/max(deg,1)) * sum_s h[s]
__global__ void k_sage_mean(const float* __restrict__ h, float* __restrict__ out) {
    int w = (blockIdx.x * blockDim.x + threadIdx.x) >> 5;
    int lane = threadIdx.x & 31;
    if (w >= NN) return;
    int start = g_rowptr[w], end = g_rowptr[w + 1];
    float4 acc = make_float4(0.f, 0.f, 0.f, 0.f);
    for (int j = start; j < end; j++) {
        int s = g_csr[j];
        float4 v = *(const float4*)(h + (size_t)s * DD + lane * 4);
        acc.x += v.x; acc.y += v.y; acc.z += v.z; acc.w += v.w;
    }
    float c = g_sinv[w];
    acc.x *= c; acc.y *= c; acc.z *= c; acc.w *= c;
    *(float4*)(out + (size_t)w * DD + lane * 4) = acc;
}

// per-node attention logits
__global__ void k_alpha(const float* __restrict__ t, const float* __restrict__ a_s,
                        const float* __restrict__ a_d) {
    int w = (blockIdx.x * blockDim.x + threadIdx.x) >> 5;
    int lane = threadIdx.x & 31;
    if (w >= NN) return;
    float4 tv = *(const float4*)(t + (size_t)w * DD + lane * 4);
    float4 sv = *(const float4*)(a_s + lane * 4);
    float4 dv = *(const float4*)(a_d + lane * 4);
    float ss = tv.x * sv.x + tv.y * sv.y + tv.z * sv.z + tv.w * sv.w;
    float dd = tv.x * dv.x + tv.y * dv.y + tv.z * dv.z + tv.w * dv.w;
#pragma unroll
    for (int off = 16; off > 0; off >>= 1) {
        ss += __shfl_down_sync(0xffffffffu, ss, off);
        dd += __shfl_down_sync(0xffffffffu, dd, off);
    }
    if (lane == 0) { g_as[w] = ss; g_ad[w] = dd; }
}

// GAT: full edge-softmax + weighted gather + bias + relu, one warp per node
__global__ void k_gat(const float* __restrict__ h, float* __restrict__ out,
                      const float* __restrict__ bias) {
    int w = (blockIdx.x * blockDim.x + threadIdx.x) >> 5;
    int lane = threadIdx.x & 31;
    if (w >= NN) return;
    float ad_d = g_ad[w];
    float as_d = g_as[w];
    int start = g_rowptr[w], end = g_rowptr[w + 1];

    // pass 1: online softmax (max + denom) over incoming edges, lanes strided
    const float NEG = -1e30f;
    float m_l = NEG, s_l = 0.f;
    for (int j = start + lane; j < end; j += 32) {
        int s = g_csr[j];
        float e = leaky(g_as[s] + ad_d);
        if (e > m_l) { s_l *= __expf(m_l - e); m_l = e; }
        s_l += __expf(e - m_l);
    }
#pragma unroll
    for (int off = 16; off > 0; off >>= 1) {
        float m_o = __shfl_xor_sync(0xffffffffu, m_l, off);
        float s_o = __shfl_xor_sync(0xffffffffu, s_l, off);
        float m_n = fmaxf(m_l, m_o);
        s_l = s_l * __expf(m_l - m_n) + s_o * __expf(m_o - m_n);
        m_l = m_n;
    }
    float e_self = leaky(as_d + ad_d);
    float m = fmaxf(m_l, e_self);
    float den = s_l * __expf(m_l - m) + __expf(e_self - m);
    float inv_den = 1.0f / den;

    // pass 2: weighted feature gather
    float wself = __expf(e_self - m) * inv_den;
    float4 acc = *(const float4*)(h + (size_t)w * DD + lane * 4);
    acc.x *= wself; acc.y *= wself; acc.z *= wself; acc.w *= wself;
    for (int j = start; j < end; j++) {
        int s = g_csr[j];
        float wgt = __expf(leaky(g_as[s] + ad_d) - m) * inv_den;
        float4 v = *(const float4*)(h + (size_t)s * DD + lane * 4);
        acc.x = fmaf(wgt, v.x, acc.x); acc.y = fmaf(wgt, v.y, acc.y);
        acc.z = fmaf(wgt, v.z, acc.z); acc.w = fmaf(wgt, v.w, acc.w);
    }
    float4 b = ((const float4*)bias)[lane];
    acc.x = fmaxf(acc.x + b.x, 0.f); acc.y = fmaxf(acc.y + b.y, 0.f);
    acc.z = fmaxf(acc.z + b.z, 0.f); acc.w = fmaxf(acc.w + b.w, 0.f);
    *(float4*)(out + (size_t)w * DD + lane * 4) = acc;
}

// output GCN (OUT=64): out = bo + dinv[d]^2*t[d] + sum dinv[s]dinv[d]*t[s]
__global__ void k_out_gather(const float* __restrict__ t, float* __restrict__ out,
                             const float* __restrict__ bias) {
    int w = (blockIdx.x * blockDim.x + threadIdx.x) >> 5;
    int lane = threadIdx.x & 31;
    if (w >= NN) return;
    float di = g_dinv[w];
    int start = g_rowptr[w], end = g_rowptr[w + 1];
    float2 acc = *(const float2*)(t + (size_t)w * OO + lane * 2);
    float cs = di * di;
    acc.x *= cs; acc.y *= cs;
    for (int j = start; j < end; j++) {
        int s = g_csr[j];
        float c = g_dinv[s] * di;
        float2 v = *(const float2*)(t + (size_t)s * OO + lane * 2);
        acc.x = fmaf(c, v.x, acc.x); acc.y = fmaf(c, v.y, acc.y);
    }
    float2 b = ((const float2*)bias)[lane];
    acc.x += b.x; acc.y += b.y;
    *(float2*)(out + (size_t)w * OO + lane * 2) = acc;
}

// ---------------- launch ----------------
extern "C" void kernel_launch(void* const* d_in, const int* in_sizes, int n_in,
                              void* d_out, int out_size) {
    const float* x  = (const float*)d_in[0];
    const void*  ei = d_in[1];
    const float* W1 = (const float*)d_in[2];
    const float* b1 = (const float*)d_in[3];
    const float* Wl = (const float*)d_in[4];
    const float* Wr = (const float*)d_in[5];
    const float* bs = (const float*)d_in[6];
    const float* Wg = (const float*)d_in[7];
    const float* a_s = (const float*)d_in[8];
    const float* a_d = (const float*)d_in[9];
    const float* bg = (const float*)d_in[10];
    const float* Wo = (const float*)d_in[11];
    const float* bo = (const float*)d_in[12];
    float* out = (float*)d_out;

    float *p_t, *p_h, *p_agg; int* p_deg;
    cudaGetSymbolAddress((void**)&p_t, g_t);
    cudaGetSymbolAddress((void**)&p_h, g_h);
    cudaGetSymbolAddress((void**)&p_agg, g_agg);
    cudaGetSymbolAddress((void**)&p_deg, g_deg);

    const int TB = 256;
    const int bN   = (NN + TB - 1) / TB;
    const int bE   = NE / TB;
    const int bNW  = (NN * 32 + TB - 1) / TB;   // warp-per-node grids
    const int gGemm = (NN + 127) / 128;

    // setup: degrees + CSR
    k_detect<<<1, 1>>>((const long long*)ei);
    k_zero_i<<<bN, TB>>>(p_deg, NN);
    k_deg<<<bE, TB>>>(ei);
    k_scal<<<bN, TB>>>();
    k_scan<<<1, 1024>>>();
    k_fill<<<bE, TB>>>(ei);

    // ---- layer 1: GCN + relu ----
    k_gemm<128, 8, false, false><<<gGemm, TB>>>(x, W1, p_t, nullptr);
    k_gcn_gather<<<bNW, TB>>>(p_t, p_h, b1);                       // h1 in g_h

    // ---- layer 2: SAGE(mean) + relu ----
    k_sage_mean<<<bNW, TB>>>(p_h, p_agg);
    k_gemm_sage<<<gGemm, TB>>>(p_agg, Wl, p_h, Wr, p_t, bs);       // h2 in g_t

    // ---- layer 3: GAT + relu ----
    k_gemm<128, 8, false, false><<<gGemm, TB>>>(p_t, Wg, p_agg, nullptr);
    k_alpha<<<bNW, TB>>>(p_agg, a_s, a_d);
    k_gat<<<bNW, TB>>>(p_agg, p_h, bg);                            // h3 in g_h

    // ---- layer 4: GCN output ----
    k_gemm<64, 4, false, false><<<gGemm, TB>>>(p_h, Wo, p_t, nullptr);
    k_out_gather<<<bNW, TB>>>(p_t, out, bo);
}

// round 5
// speedup vs baseline: 1.8552x; 1.0196x over previous
#include <cuda_runtime.h>
#include <cuda_bf16.h>
#include <math.h>
#include <stdint.h>

#define NN 50000
#define NE 1600000
#define DD 128
#define OO 64

// ---------------- device scratch ----------------
__device__ int   g_is64;
__device__ int   g_deg[NN];
__device__ float g_dinv[NN];
__device__ float g_sinv[NN];
__device__ float g_as[NN];
__device__ float g_ad[NN];
__device__ int   g_rowptr[NN + 1];
__device__ int   g_cur[NN];
__device__ int   g_csr[NE];
__device__ float g_t[(size_t)NN * DD];
__device__ float g_h[(size_t)NN * DD];
__device__ float g_agg[(size_t)NN * DD];

__device__ __forceinline__ float leaky(float v) { return v > 0.f ? v : 0.2f * v; }

__device__ __forceinline__ void edge_ld(const void* ei, int e, int& s, int& d) {
    if (g_is64) {
        const long long* p = (const long long*)ei;
        s = (int)p[e]; d = (int)p[NE + e];
    } else {
        const int* p = (const int*)ei;
        s = p[e]; d = p[NE + e];
    }
}

// ---------------- setup ----------------
__global__ void k_detect(const long long* ei) {
    bool is64 = true;
    for (int i = 0; i < 64; i++) {
        long long v = ei[i];
        if (v < 0 || v >= NN) { is64 = false; break; }
    }
    g_is64 = is64 ? 1 : 0;
}

__global__ void k_zero_i(int* p, int n) {
    int i = blockIdx.x * blockDim.x + threadIdx.x;
    if (i < n) p[i] = 0;
}

__global__ void k_deg(const void* ei) {
    int e = blockIdx.x * blockDim.x + threadIdx.x;
    if (e >= NE) return;
    int s, d; edge_ld(ei, e, s, d);
    atomicAdd(&g_deg[d], 1);
}

__global__ void k_scal() {
    int i = blockIdx.x * blockDim.x + threadIdx.x;
    if (i >= NN) return;
    int deg = g_deg[i];
    g_dinv[i] = rsqrtf((float)(deg + 1));
    g_sinv[i] = 1.0f / (float)max(deg, 1);
}

// single-block exclusive scan of g_deg -> g_rowptr, also init g_cur
__global__ void __launch_bounds__(1024) k_scan() {
    __shared__ int sh[1024];
    __shared__ int sh_carry;
    int tid = threadIdx.x;
    if (tid == 0) { sh_carry = 0; g_rowptr[0] = 0; }
    __syncthreads();
    for (int base = 0; base < NN; base += 1024) {
        int i = base + tid;
        int v = (i < NN) ? g_deg[i] : 0;
        sh[tid] = v;
        __syncthreads();
#pragma unroll
        for (int off = 1; off < 1024; off <<= 1) {
            int t = (tid >= off) ? sh[tid - off] : 0;
            __syncthreads();
            sh[tid] += t;
            __syncthreads();
        }
        int carry = sh_carry;
        if (i < NN) {
            int excl = carry + sh[tid] - v;
            g_rowptr[i + 1] = carry + sh[tid];
            g_cur[i] = excl;
        }
        __syncthreads();
        if (tid == 0) sh_carry = carry + sh[1023];
        __syncthreads();
    }
}

__global__ void k_fill(const void* ei) {
    int e = blockIdx.x * blockDim.x + threadIdx.x;
    if (e >= NE) return;
    int s, d; edge_ld(ei, e, s, d);
    int pos = atomicAdd(&g_cur[d], 1);
    g_csr[pos] = s;
}

// ---------------- tensor-core GEMM (split-bf16 x3 emulation of fp32) ----------------
// C[NN x BN] = A[NN x 128] @ B[128 x BN] (+ A2@B2 if TWO) (+bias) (relu)
// mma.sync.m16n8k16.bf16, fp32 accum. hi*hi + hi*lo + lo*hi.
__device__ __forceinline__ void mma16816(float* c, const uint32_t* a, const uint32_t* b) {
    asm volatile(
        "mma.sync.aligned.m16n8k16.row.col.f32.bf16.bf16.f32 "
        "{%0,%1,%2,%3}, {%4,%5,%6,%7}, {%8,%9}, {%0,%1,%2,%3};"
        : "+f"(c[0]), "+f"(c[1]), "+f"(c[2]), "+f"(c[3])
        : "r"(a[0]), "r"(a[1]), "r"(a[2]), "r"(a[3]), "r"(b[0]), "r"(b[1]));
}

template<int BN, bool TWO, bool BIAS, bool RELU>
__global__ void __launch_bounds__(256) k_gemm_tc(
        const float* __restrict__ A1, const float* __restrict__ B1,
        const float* __restrict__ A2, const float* __restrict__ B2,
        float* __restrict__ C, const float* __restrict__ bias) {
    constexpr int BM = 128, BK = 16;
    constexpr int MWARPS = (BN == 128) ? 2 : 4;   // warps along M
    constexpr int MW = BM / MWARPS;               // 64 or 32
    constexpr int MT = MW / 16;                   // 4 or 2
    constexpr int NT = 4;                         // NW = 32 always
    constexpr int LD = 24;                        // padded stride in bf16 units

    __shared__ __nv_bfloat16 As_hi[BM][LD];
    __shared__ __nv_bfloat16 As_lo[BM][LD];
    __shared__ __nv_bfloat16 Bs_hi[BN][LD];
    __shared__ __nv_bfloat16 Bs_lo[BN][LD];

    const int tid = threadIdx.x;
    const int wid = tid >> 5;
    const int lane = tid & 31;
    const int g = lane >> 2;
    const int t = lane & 3;
    const int wm = wid % MWARPS;
    const int wn = wid / MWARPS;
    const int m0 = blockIdx.x * BM;
    const int m0w = wm * MW;
    const int n0w = wn * 32;

    float c[MT][NT][4];
#pragma unroll
    for (int i = 0; i < MT; i++)
#pragma unroll
        for (int j = 0; j < NT; j++)
#pragma unroll
            for (int q = 0; q < 4; q++) c[i][j][q] = 0.f;

    const int NPH = TWO ? 2 : 1;
    for (int ph = 0; ph < NPH; ph++) {
        const float* A = (TWO && ph) ? A2 : A1;
        const float* B = (TWO && ph) ? B2 : B1;
        for (int k0 = 0; k0 < DD; k0 += BK) {
            // ---- fill A tile: BM x BK, split hi/lo ----
#pragma unroll
            for (int l = 0; l < 2; l++) {
                int i4 = tid + l * 256;          // 512 float4 total
                int m = i4 >> 2;
                int k = (i4 & 3) * 4;
                int gr = m0 + m;
                float4 v = make_float4(0.f, 0.f, 0.f, 0.f);
                if (gr < NN) v = *(const float4*)(A + (size_t)gr * DD + k0 + k);
                __nv_bfloat162 h0 = __float22bfloat162_rn(make_float2(v.x, v.y));
                __nv_bfloat162 h1 = __float22bfloat162_rn(make_float2(v.z, v.w));
                float2 r0 = make_float2(v.x - __bfloat162float(h0.x),
                                        v.y - __bfloat162float(h0.y));
                float2 r1 = make_float2(v.z - __bfloat162float(h1.x),
                                        v.w - __bfloat162float(h1.y));
                __nv_bfloat162 l0 = __float22bfloat162_rn(r0);
                __nv_bfloat162 l1 = __float22bfloat162_rn(r1);
                *(__nv_bfloat162*)&As_hi[m][k]     = h0;
                *(__nv_bfloat162*)&As_hi[m][k + 2] = h1;
                *(__nv_bfloat162*)&As_lo[m][k]     = l0;
                *(__nv_bfloat162*)&As_lo[m][k + 2] = l1;
            }
            // ---- fill B tile: BK x BN, transposed store [n][k], split hi/lo ----
            constexpr int NB4 = (BK * BN) / 1024;  // float4 loads per thread (2 or 1)
#pragma unroll
            for (int l = 0; l < NB4; l++) {
                int i4 = tid + l * 256;
                int k = i4 / (BN / 4);
                int n = (i4 % (BN / 4)) * 4;
                float4 v = *(const float4*)(B + (size_t)(k0 + k) * BN + n);
                float vv[4] = {v.x, v.y, v.z, v.w};
#pragma unroll
                for (int q = 0; q < 4; q++) {
                    __nv_bfloat16 h = __float2bfloat16_rn(vv[q]);
                    Bs_hi[n + q][k] = h;
                    Bs_lo[n + q][k] = __float2bfloat16_rn(vv[q] - __bfloat162float(h));
                }
            }
            __syncthreads();

            // ---- load fragments + mma (one k16 step) ----
            uint32_t bh[NT][2], bl[NT][2];
#pragma unroll
            for (int nt = 0; nt < NT; nt++) {
                int nr = n0w + nt * 8 + g;
                bh[nt][0] = *(const uint32_t*)&Bs_hi[nr][2 * t];
                bh[nt][1] = *(const uint32_t*)&Bs_hi[nr][2 * t + 8];
                bl[nt][0] = *(const uint32_t*)&Bs_lo[nr][2 * t];
                bl[nt][1] = *(const uint32_t*)&Bs_lo[nr][2 * t + 8];
            }
#pragma unroll
            for (int mt = 0; mt < MT; mt++) {
                int mr = m0w + mt * 16 + g;
                uint32_t ah[4], al[4];
                ah[0] = *(const uint32_t*)&As_hi[mr][2 * t];
                ah[1] = *(const uint32_t*)&As_hi[mr + 8][2 * t];
                ah[2] = *(const uint32_t*)&As_hi[mr][2 * t + 8];
                ah[3] = *(const uint32_t*)&As_hi[mr + 8][2 * t + 8];
                al[0] = *(const uint32_t*)&As_lo[mr][2 * t];
                al[1] = *(const uint32_t*)&As_lo[mr + 8][2 * t];
                al[2] = *(const uint32_t*)&As_lo[mr][2 * t + 8];
                al[3] = *(const uint32_t*)&As_lo[mr + 8][2 * t + 8];
#pragma unroll
                for (int nt = 0; nt < NT; nt++) {
                    mma16816(c[mt][nt], ah, bh[nt]);
                    mma16816(c[mt][nt], ah, bl[nt]);
                    mma16816(c[mt][nt], al, bh[nt]);
                }
            }
            __syncthreads();
        }
    }

    // ---- epilogue ----
#pragma unroll
    for (int mt = 0; mt < MT; mt++) {
#pragma unroll
        for (int nt = 0; nt < NT; nt++) {
            int row = m0 + m0w + mt * 16 + g;
            int col = n0w + nt * 8 + 2 * t;
            float2 b2 = make_float2(0.f, 0.f);
            if (BIAS) b2 = *(const float2*)(bias + col);
            if (row < NN) {
                float2 v = make_float2(c[mt][nt][0] + b2.x, c[mt][nt][1] + b2.y);
                if (RELU) { v.x = fmaxf(v.x, 0.f); v.y = fmaxf(v.y, 0.f); }
                *(float2*)(C + (size_t)row * BN + col) = v;
            }
            if (row + 8 < NN) {
                float2 v = make_float2(c[mt][nt][2] + b2.x, c[mt][nt][3] + b2.y);
                if (RELU) { v.x = fmaxf(v.x, 0.f); v.y = fmaxf(v.y, 0.f); }
                *(float2*)(C + (size_t)(row + 8) * BN + col) = v;
            }
        }
    }
}

// ---------------- CSR gather kernels (warp per node, unroll-2) ----------------
__global__ void k_gcn_gather(const float* __restrict__ t, float* __restrict__ out,
                             const float* __restrict__ bias) {
    int w = (blockIdx.x * blockDim.x + threadIdx.x) >> 5;
    int lane = threadIdx.x & 31;
    if (w >= NN) return;
    float di = g_dinv[w];
    int start = g_rowptr[w], end = g_rowptr[w + 1];
    float4 acc = *(const float4*)(t + (size_t)w * DD + lane * 4);
    float cs = di * di;
    acc.x *= cs; acc.y *= cs; acc.z *= cs; acc.w *= cs;
    float4 acc2 = make_float4(0.f, 0.f, 0.f, 0.f);
    int j = start;
    for (; j + 2 <= end; j += 2) {
        int s0 = g_csr[j], s1 = g_csr[j + 1];
        float c0 = g_dinv[s0] * di, c1 = g_dinv[s1] * di;
        float4 v0 = *(const float4*)(t + (size_t)s0 * DD + lane * 4);
        float4 v1 = *(const float4*)(t + (size_t)s1 * DD + lane * 4);
        acc.x = fmaf(c0, v0.x, acc.x);  acc.y = fmaf(c0, v0.y, acc.y);
        acc.z = fmaf(c0, v0.z, acc.z);  acc.w = fmaf(c0, v0.w, acc.w);
        acc2.x = fmaf(c1, v1.x, acc2.x); acc2.y = fmaf(c1, v1.y, acc2.y);
        acc2.z = fmaf(c1, v1.z, acc2.z); acc2.w = fmaf(c1, v1.w, acc2.w);
    }
    if (j < end) {
        int s = g_csr[j];
        float cc = g_dinv[s] * di;
        float4 v = *(const float4*)(t + (size_t)s * DD + lane * 4);
        acc.x = fmaf(cc, v.x, acc.x); acc.y = fmaf(cc, v.y, acc.y);
        acc.z = fmaf(cc, v.z, acc.z); acc.w = fmaf(cc, v.w, acc.w);
    }
    acc.x += acc2.x; acc.y += acc2.y; acc.z += acc2.z; acc.w += acc2.w;
    float4 b = ((const float4*)bias)[lane];
    acc.x = fmaxf(acc.x + b.x, 0.f); acc.y = fmaxf(acc.y + b.y, 0.f);
    acc.z = fmaxf(acc.z + b.z, 0.f); acc.w = fmaxf(acc.w + b.w, 0.f);
    *(float4*)(out + (size_t)w * DD + lane * 4) = acc;
}

__global__ void k_sage_mean(const float* __restrict__ h, float* __restrict__ out) {
    int w = (blockIdx.x * blockDim.x + threadIdx.x) >> 5;
    int lane = threadIdx.x & 31;
    if (w >= NN) return;
    int start = g_rowptr[w], end = g_rowptr[w + 1];
    float4 acc = make_float4(0.f, 0.f, 0.f, 0.f);
    float4 acc2 = make_float4(0.f, 0.f, 0.f, 0.f);
    int j = start;
    for (; j + 2 <= end; j += 2) {
        int s0 = g_csr[j], s1 = g_csr[j + 1];
        float4 v0 = *(const float4*)(h + (size_t)s0 * DD + lane * 4);
        float4 v1 = *(const float4*)(h + (size_t)s1 * DD + lane * 4);
        acc.x += v0.x; acc.y += v0.y; acc.z += v0.z; acc.w += v0.w;
        acc2.x += v1.x; acc2.y += v1.y; acc2.z += v1.z; acc2.w += v1.w;
    }
    if (j < end) {
        int s = g_csr[j];
        float4 v = *(const float4*)(h + (size_t)s * DD + lane * 4);
        acc.x += v.x; acc.y += v.y; acc.z += v.z; acc.w += v.w;
    }
    float cc = g_sinv[w];
    acc.x = (acc.x + acc2.x) * cc; acc.y = (acc.y + acc2.y) * cc;
    acc.z = (acc.z + acc2.z) * cc; acc.w = (acc.w + acc2.w) * cc;
    *(float4*)(out + (size_t)w * DD + lane * 4) = acc;
}

__global__ void k_alpha(const float* __restrict__ t, const float* __restrict__ a_s,
                        const float* __restrict__ a_d) {
    int w = (blockIdx.x * blockDim.x + threadIdx.x) >> 5;
    int lane = threadIdx.x & 31;
    if (w >= NN) return;
    float4 tv = *(const float4*)(t + (size_t)w * DD + lane * 4);
    float4 sv = *(const float4*)(a_s + lane * 4);
    float4 dv = *(const float4*)(a_d + lane * 4);
    float ss = tv.x * sv.x + tv.y * sv.y + tv.z * sv.z + tv.w * sv.w;
    float dd = tv.x * dv.x + tv.y * dv.y + tv.z * dv.z + tv.w * dv.w;
#pragma unroll
    for (int off = 16; off > 0; off >>= 1) {
        ss += __shfl_down_sync(0xffffffffu, ss, off);
        dd += __shfl_down_sync(0xffffffffu, dd, off);
    }
    if (lane == 0) { g_as[w] = ss; g_ad[w] = dd; }
}

__global__ void k_gat(const float* __restrict__ h, float* __restrict__ out,
                      const float* __restrict__ bias) {
    int w = (blockIdx.x * blockDim.x + threadIdx.x) >> 5;
    int lane = threadIdx.x & 31;
    if (w >= NN) return;
    float ad_d = g_ad[w];
    float as_d = g_as[w];
    int start = g_rowptr[w], end = g_rowptr[w + 1];

    const float NEG = -1e30f;
    float m_l = NEG, s_l = 0.f;
    for (int j = start + lane; j < end; j += 32) {
        int s = g_csr[j];
        float e = leaky(g_as[s] + ad_d);
        if (e > m_l) { s_l *= __expf(m_l - e); m_l = e; }
        s_l += __expf(e - m_l);
    }
#pragma unroll
    for (int off = 16; off > 0; off >>= 1) {
        float m_o = __shfl_xor_sync(0xffffffffu, m_l, off);
        float s_o = __shfl_xor_sync(0xffffffffu, s_l, off);
        float m_n = fmaxf(m_l, m_o);
        s_l = s_l * __expf(m_l - m_n) + s_o * __expf(m_o - m_n);
        m_l = m_n;
    }
    float e_self = leaky(as_d + ad_d);
    float m = fmaxf(m_l, e_self);
    float den = s_l * __expf(m_l - m) + __expf(e_self - m);
    float inv_den = 1.0f / den;

    float wself = __expf(e_self - m) * inv_den;
    float4 acc = *(const float4*)(h + (size_t)w * DD + lane * 4);
    acc.x *= wself; acc.y *= wself; acc.z *= wself; acc.w *= wself;
    float4 acc2 = make_float4(0.f, 0.f, 0.f, 0.f);
    int j = start;
    for (; j + 2 <= end; j += 2) {
        int s0 = g_csr[j], s1 = g_csr[j + 1];
        float w0 = __expf(leaky(g_as[s0] + ad_d) - m) * inv_den;
        float w1 = __expf(leaky(g_as[s1] + ad_d) - m) * inv_den;
        float4 v0 = *(const float4*)(h + (size_t)s0 * DD + lane * 4);
        float4 v1 = *(const float4*)(h + (size_t)s1 * DD + lane * 4);
        acc.x = fmaf(w0, v0.x, acc.x);  acc.y = fmaf(w0, v0.y, acc.y);
        acc.z = fmaf(w0, v0.z, acc.z);  acc.w = fmaf(w0, v0.w, acc.w);
        acc2.x = fmaf(w1, v1.x, acc2.x); acc2.y = fmaf(w1, v1.y, acc2.y);
        acc2.z = fmaf(w1, v1.z, acc2.z); acc2.w = fmaf(w1, v1.w, acc2.w);
    }
    if (j < end) {
        int s = g_csr[j];
        float wgt = __expf(leaky(g_as[s] + ad_d) - m) * inv_den;
        float4 v = *(const float4*)(h + (size_t)s * DD + lane * 4);
        acc.x = fmaf(wgt, v.x, acc.x); acc.y = fmaf(wgt, v.y, acc.y);
        acc.z = fmaf(wgt, v.z, acc.z); acc.w = fmaf(wgt, v.w, acc.w);
    }
    acc.x += acc2.x; acc.y += acc2.y; acc.z += acc2.z; acc.w += acc2.w;
    float4 b = ((const float4*)bias)[lane];
    acc.x = fmaxf(acc.x + b.x, 0.f); acc.y = fmaxf(acc.y + b.y, 0.f);
    acc.z = fmaxf(acc.z + b.z, 0.f); acc.w = fmaxf(acc.w + b.w, 0.f);
    *(float4*)(out + (size_t)w * DD + lane * 4) = acc;
}

__global__ void k_out_gather(const float* __restrict__ t, float* __restrict__ out,
                             const float* __restrict__ bias) {
    int w = (blockIdx.x * blockDim.x + threadIdx.x) >> 5;
    int lane = threadIdx.x & 31;
    if (w >= NN) return;
    float di = g_dinv[w];
    int start = g_rowptr[w], end = g_rowptr[w + 1];
    float2 acc = *(const float2*)(t + (size_t)w * OO + lane * 2);
    float cs = di * di;
    acc.x *= cs; acc.y *= cs;
    float2 acc2 = make_float2(0.f, 0.f);
    int j = start;
    for (; j + 2 <= end; j += 2) {
        int s0 = g_csr[j], s1 = g_csr[j + 1];
        float c0 = g_dinv[s0] * di, c1 = g_dinv[s1] * di;
        float2 v0 = *(const float2*)(t + (size_t)s0 * OO + lane * 2);
        float2 v1 = *(const float2*)(t + (size_t)s1 * OO + lane * 2);
        acc.x = fmaf(c0, v0.x, acc.x);   acc.y = fmaf(c0, v0.y, acc.y);
        acc2.x = fmaf(c1, v1.x, acc2.x); acc2.y = fmaf(c1, v1.y, acc2.y);
    }
    if (j < end) {
        int s = g_csr[j];
        float cc = g_dinv[s] * di;
        float2 v = *(const float2*)(t + (size_t)s * OO + lane * 2);
        acc.x = fmaf(cc, v.x, acc.x); acc.y = fmaf(cc, v.y, acc.y);
    }
    float2 b = ((const float2*)bias)[lane];
    acc.x += acc2.x + b.x; acc.y += acc2.y + b.y;
    *(float2*)(out + (size_t)w * OO + lane * 2) = acc;
}

// ---------------- launch ----------------
extern "C" void kernel_launch(void* const* d_in, const int* in_sizes, int n_in,
                              void* d_out, int out_size) {
    const float* x  = (const float*)d_in[0];
    const void*  ei = d_in[1];
    const float* W1 = (const float*)d_in[2];
    const float* b1 = (const float*)d_in[3];
    const float* Wl = (const float*)d_in[4];
    const float* Wr = (const float*)d_in[5];
    const float* bs = (const float*)d_in[6];
    const float* Wg = (const float*)d_in[7];
    const float* a_s = (const float*)d_in[8];
    const float* a_d = (const float*)d_in[9];
    const float* bg = (const float*)d_in[10];
    const float* Wo = (const float*)d_in[11];
    const float* bo = (const float*)d_in[12];
    float* out = (float*)d_out;

    float *p_t, *p_h, *p_agg; int* p_deg;
    cudaGetSymbolAddress((void**)&p_t, g_t);
    cudaGetSymbolAddress((void**)&p_h, g_h);
    cudaGetSymbolAddress((void**)&p_agg, g_agg);
    cudaGetSymbolAddress((void**)&p_deg, g_deg);

    const int TB = 256;
    const int bN   = (NN + TB - 1) / TB;
    const int bE   = NE / TB;
    const int bNW  = (NN * 32 + TB - 1) / TB;   // warp-per-node grids
    const int gGemm = (NN + 127) / 128;

    // setup: degrees + CSR
    k_detect<<<1, 1>>>((const long long*)ei);
    k_zero_i<<<bN, TB>>>(p_deg, NN);
    k_deg<<<bE, TB>>>(ei);
    k_scal<<<bN, TB>>>();
    k_scan<<<1, 1024>>>();
    k_fill<<<bE, TB>>>(ei);

    // ---- layer 1: GCN + relu ----
    k_gemm_tc<128, false, false, false><<<gGemm, TB>>>(x, W1, nullptr, nullptr, p_t, nullptr);
    k_gcn_gather<<<bNW, TB>>>(p_t, p_h, b1);                       // h1 in g_h

    // ---- layer 2: SAGE(mean) + relu ----
    k_sage_mean<<<bNW, TB>>>(p_h, p_agg);
    k_gemm_tc<128, true, true, true><<<gGemm, TB>>>(p_agg, Wl, p_h, Wr, p_t, bs);  // h2 in g_t

    // ---- layer 3: GAT + relu ----
    k_gemm_tc<128, false, false, false><<<gGemm, TB>>>(p_t, Wg, nullptr, nullptr, p_agg, nullptr);
    k_alpha<<<bNW, TB>>>(p_agg, a_s, a_d);
    k_gat<<<bNW, TB>>>(p_agg, p_h, bg);                            // h3 in g_h

    // ---- layer 4: GCN output ----
    k_gemm_tc<64, false, false, false><<<gGemm, TB>>>(p_h, Wo, nullptr, nullptr, p_t, nullptr);
    k_out_gather<<<bNW, TB>>>(p_t, out, bo);
}

// round 6
// speedup vs baseline: 2.1200x; 1.1428x over previous
#include <cuda_runtime.h>
#include <cuda_bf16.h>
#include <math.h>
#include <stdint.h>

#define NN 50000
#define NE 1600000
#define DD 128
#define OO 64

typedef __nv_bfloat16 bf16;
typedef __nv_bfloat162 bf162;

// ---------------- device scratch ----------------
__device__ int   g_is64;
__device__ int   g_deg[NN];
__device__ float g_dinv[NN];
__device__ float g_sinv[NN];
__device__ float g_as[NN];
__device__ float g_ad[NN];
__device__ int   g_rowptr[NN + 1];
__device__ int   g_cur[NN];
__device__ int   g_csr[NE];
__device__ float g_t[(size_t)NN * DD];
__device__ float g_h[(size_t)NN * DD];
__device__ float g_agg[(size_t)NN * DD];
// split-bf16 feature buffers (3 ping-pong pairs)
__device__ bf16  g_p0h[(size_t)NN * DD];
__device__ bf16  g_p0l[(size_t)NN * DD];
__device__ bf16  g_p1h[(size_t)NN * DD];
__device__ bf16  g_p1l[(size_t)NN * DD];
__device__ bf16  g_p2h[(size_t)NN * DD];
__device__ bf16  g_p2l[(size_t)NN * DD];
// split + transposed weights: [n][k], k=128. Offsets below.
#define WOFF_W1 0
#define WOFF_WL 16384
#define WOFF_WR 32768
#define WOFF_WG 49152
#define WOFF_WO 65536
__device__ bf16  g_wh[73728];
__device__ bf16  g_wl[73728];

__device__ __forceinline__ float leaky(float v) { return v > 0.f ? v : 0.2f * v; }

__device__ __forceinline__ void edge_ld(const void* ei, int e, int& s, int& d) {
    if (g_is64) {
        const long long* p = (const long long*)ei;
        s = (int)p[e]; d = (int)p[NE + e];
    } else {
        const int* p = (const int*)ei;
        s = p[e]; d = p[NE + e];
    }
}

__device__ __forceinline__ void split2(float x, float y, bf162& hi, bf162& lo) {
    hi = __float22bfloat162_rn(make_float2(x, y));
    lo = __float22bfloat162_rn(make_float2(x - __bfloat162float(hi.x),
                                           y - __bfloat162float(hi.y)));
}

// ---------------- setup ----------------
__global__ void k_detect(const long long* ei) {
    bool is64 = true;
    for (int i = 0; i < 64; i++) {
        long long v = ei[i];
        if (v < 0 || v >= NN) { is64 = false; break; }
    }
    g_is64 = is64 ? 1 : 0;
}

__global__ void k_zero_i(int* p, int n) {
    int i = blockIdx.x * blockDim.x + threadIdx.x;
    if (i < n) p[i] = 0;
}

__global__ void k_deg(const void* ei) {
    int e = blockIdx.x * blockDim.x + threadIdx.x;
    if (e >= NE) return;
    int s, d; edge_ld(ei, e, s, d);
    atomicAdd(&g_deg[d], 1);
}

__global__ void k_scal() {
    int i = blockIdx.x * blockDim.x + threadIdx.x;
    if (i >= NN) return;
    int deg = g_deg[i];
    g_dinv[i] = rsqrtf((float)(deg + 1));
    g_sinv[i] = 1.0f / (float)max(deg, 1);
}

__global__ void __launch_bounds__(1024) k_scan() {
    __shared__ int sh[1024];
    __shared__ int sh_carry;
    int tid = threadIdx.x;
    if (tid == 0) { sh_carry = 0; g_rowptr[0] = 0; }
    __syncthreads();
    for (int base = 0; base < NN; base += 1024) {
        int i = base + tid;
        int v = (i < NN) ? g_deg[i] : 0;
        sh[tid] = v;
        __syncthreads();
#pragma unroll
        for (int off = 1; off < 1024; off <<= 1) {
            int t = (tid >= off) ? sh[tid - off] : 0;
            __syncthreads();
            sh[tid] += t;
            __syncthreads();
        }
        int carry = sh_carry;
        if (i < NN) {
            int excl = carry + sh[tid] - v;
            g_rowptr[i + 1] = carry + sh[tid];
            g_cur[i] = excl;
        }
        __syncthreads();
        if (tid == 0) sh_carry = carry + sh[1023];
        __syncthreads();
    }
}

__global__ void k_fill(const void* ei) {
    int e = blockIdx.x * blockDim.x + threadIdx.x;
    if (e >= NE) return;
    int s, d; edge_ld(ei, e, s, d);
    int pos = atomicAdd(&g_cur[d], 1);
    g_csr[pos] = s;
}

// ---------------- one-shot split kernels ----------------
// weight: src [K x N] row-major -> dst [N x K] (transposed), split hi/lo
__global__ void k_convw(const float* __restrict__ src, bf16* __restrict__ h,
                        bf16* __restrict__ l, int K, int N) {
    int i = blockIdx.x * blockDim.x + threadIdx.x;
    if (i >= K * N) return;
    int k = i / N, n = i % N;
    float v = src[i];
    bf16 hi = __float2bfloat16_rn(v);
    h[n * K + k] = hi;
    l[n * K + k] = __float2bfloat16_rn(v - __bfloat162float(hi));
}

// features: src fp32 -> hi/lo, same layout. i indexes float4.
__global__ void k_split4(const float* __restrict__ src, bf16* __restrict__ h,
                         bf16* __restrict__ l, int n4) {
    int i = blockIdx.x * blockDim.x + threadIdx.x;
    if (i >= n4) return;
    float4 v = ((const float4*)src)[i];
    bf162 h0, l0, h1, l1;
    split2(v.x, v.y, h0, l0);
    split2(v.z, v.w, h1, l1);
    *(bf162*)&h[i * 4]     = h0;
    *(bf162*)&h[i * 4 + 2] = h1;
    *(bf162*)&l[i * 4]     = l0;
    *(bf162*)&l[i * 4 + 2] = l1;
}

// ---------------- tensor-core GEMM on pre-split bf16 ----------------
__device__ __forceinline__ void mma16816(float* c, const uint32_t* a, const uint32_t* b) {
    asm volatile(
        "mma.sync.aligned.m16n8k16.row.col.f32.bf16.bf16.f32 "
        "{%0,%1,%2,%3}, {%4,%5,%6,%7}, {%8,%9}, {%0,%1,%2,%3};"
        : "+f"(c[0]), "+f"(c[1]), "+f"(c[2]), "+f"(c[3])
        : "r"(a[0]), "r"(a[1]), "r"(a[2]), "r"(a[3]), "r"(b[0]), "r"(b[1]));
}

// C[NN x BN] = A[NN x 128] @ B^T (B stored [BN x 128] hi/lo) (+ A2@B2) (+bias)(relu)
// OSPLIT: write Ch/Cl bf16 instead of fp32 C.
template<int BN, bool TWO, bool BIAS, bool RELU, bool OSPLIT>
__global__ void __launch_bounds__(256) k_gemm_bf(
        const bf16* __restrict__ A1h, const bf16* __restrict__ A1l,
        const bf16* __restrict__ A2h, const bf16* __restrict__ A2l,
        const bf16* __restrict__ B1h, const bf16* __restrict__ B1l,
        const bf16* __restrict__ B2h, const bf16* __restrict__ B2l,
        float* __restrict__ C, bf16* __restrict__ Ch, bf16* __restrict__ Cl,
        const float* __restrict__ bias) {
    constexpr int BM = 128, BK = 32, LD = 40;
    constexpr int MWARPS = (BN == 128) ? 2 : 4;
    constexpr int MW = BM / MWARPS;
    constexpr int MT = MW / 16;
    constexpr int NT = 4;

    __shared__ bf16 Ah[BM][LD];
    __shared__ bf16 Al[BM][LD];
    __shared__ bf16 Bh[BN][LD];
    __shared__ bf16 Bl[BN][LD];

    const int tid = threadIdx.x;
    const int wid = tid >> 5;
    const int lane = tid & 31;
    const int g = lane >> 2;
    const int t = lane & 3;
    const int wm = wid % MWARPS;
    const int wn = wid / MWARPS;
    const int m0 = blockIdx.x * BM;
    const int m0w = wm * MW;
    const int n0w = wn * 32;

    float c[MT][NT][4];
#pragma unroll
    for (int i = 0; i < MT; i++)
#pragma unroll
        for (int j = 0; j < NT; j++)
#pragma unroll
            for (int q = 0; q < 4; q++) c[i][j][q] = 0.f;

    const int NPH = TWO ? 2 : 1;
    for (int ph = 0; ph < NPH; ph++) {
        const bf16* Aph = (TWO && ph) ? A2h : A1h;
        const bf16* Apl = (TWO && ph) ? A2l : A1l;
        const bf16* Bph = (TWO && ph) ? B2h : B1h;
        const bf16* Bpl = (TWO && ph) ? B2l : B1l;
#pragma unroll
        for (int k0 = 0; k0 < DD; k0 += BK) {
            // A tile: 128x32 bf16, uint4 (8 bf16) loads, 2 per thread per array
#pragma unroll
            for (int l = 0; l < 2; l++) {
                int idx = tid + l * 256;
                int m = idx >> 2;
                int ko = (idx & 3) * 8;
                int gr = m0 + m;
                uint4 vh = make_uint4(0, 0, 0, 0), vl = make_uint4(0, 0, 0, 0);
                if (gr < NN) {
                    vh = *(const uint4*)&Aph[(size_t)gr * DD + k0 + ko];
                    vl = *(const uint4*)&Apl[(size_t)gr * DD + k0 + ko];
                }
                *(uint4*)&Ah[m][ko] = vh;
                *(uint4*)&Al[m][ko] = vl;
            }
            // B tile: BN x 32
            constexpr int NB = (BN * BK) / (8 * 256);  // 2 or 1
#pragma unroll
            for (int l = 0; l < NB; l++) {
                int idx = tid + l * 256;
                int n = idx >> 2;
                int ko = (idx & 3) * 8;
                *(uint4*)&Bh[n][ko] = *(const uint4*)&Bph[(size_t)n * DD + k0 + ko];
                *(uint4*)&Bl[n][ko] = *(const uint4*)&Bpl[(size_t)n * DD + k0 + ko];
            }
            __syncthreads();
#pragma unroll
            for (int s = 0; s < 2; s++) {
                const int kb = s * 16;
                uint32_t bh[NT][2], bl[NT][2];
#pragma unroll
                for (int nt = 0; nt < NT; nt++) {
                    int nr = n0w + nt * 8 + g;
                    bh[nt][0] = *(const uint32_t*)&Bh[nr][kb + 2 * t];
                    bh[nt][1] = *(const uint32_t*)&Bh[nr][kb + 2 * t + 8];
                    bl[nt][0] = *(const uint32_t*)&Bl[nr][kb + 2 * t];
                    bl[nt][1] = *(const uint32_t*)&Bl[nr][kb + 2 * t + 8];
                }
#pragma unroll
                for (int mt = 0; mt < MT; mt++) {
                    int mr = m0w + mt * 16 + g;
                    uint32_t ah[4], al[4];
                    ah[0] = *(const uint32_t*)&Ah[mr][kb + 2 * t];
                    ah[1] = *(const uint32_t*)&Ah[mr + 8][kb + 2 * t];
                    ah[2] = *(const uint32_t*)&Ah[mr][kb + 2 * t + 8];
                    ah[3] = *(const uint32_t*)&Ah[mr + 8][kb + 2 * t + 8];
                    al[0] = *(const uint32_t*)&Al[mr][kb + 2 * t];
                    al[1] = *(const uint32_t*)&Al[mr + 8][kb + 2 * t];
                    al[2] = *(const uint32_t*)&Al[mr][kb + 2 * t + 8];
                    al[3] = *(const uint32_t*)&Al[mr + 8][kb + 2 * t + 8];
#pragma unroll
                    for (int nt = 0; nt < NT; nt++) {
                        mma16816(c[mt][nt], ah, bh[nt]);
                        mma16816(c[mt][nt], ah, bl[nt]);
                        mma16816(c[mt][nt], al, bh[nt]);
                    }
                }
            }
            __syncthreads();
        }
    }

    // ---- epilogue ----
#pragma unroll
    for (int mt = 0; mt < MT; mt++) {
#pragma unroll
        for (int nt = 0; nt < NT; nt++) {
            int row = m0 + m0w + mt * 16 + g;
            int col = n0w + nt * 8 + 2 * t;
            float2 b2 = make_float2(0.f, 0.f);
            if (BIAS) b2 = *(const float2*)(bias + col);
#pragma unroll
            for (int half = 0; half < 2; half++) {
                int r = row + half * 8;
                if (r >= NN) continue;
                float vx = c[mt][nt][half * 2 + 0] + b2.x;
                float vy = c[mt][nt][half * 2 + 1] + b2.y;
                if (RELU) { vx = fmaxf(vx, 0.f); vy = fmaxf(vy, 0.f); }
                if (OSPLIT) {
                    bf162 hi, lo;
                    split2(vx, vy, hi, lo);
                    *(bf162*)&Ch[(size_t)r * BN + col] = hi;
                    *(bf162*)&Cl[(size_t)r * BN + col] = lo;
                } else {
                    *(float2*)(C + (size_t)r * BN + col) = make_float2(vx, vy);
                }
            }
        }
    }
}

// ---------------- CSR gather kernels (warp per node, unroll-2) ----------------
// GCN layer 1: fp32 out + split out
__global__ void k_gcn_gather(const float* __restrict__ t, float* __restrict__ out,
                             bf16* __restrict__ oh, bf16* __restrict__ ol,
                             const float* __restrict__ bias) {
    int w = (blockIdx.x * blockDim.x + threadIdx.x) >> 5;
    int lane = threadIdx.x & 31;
    if (w >= NN) return;
    float di = g_dinv[w];
    int start = g_rowptr[w], end = g_rowptr[w + 1];
    float4 acc = *(const float4*)(t + (size_t)w * DD + lane * 4);
    float cs = di * di;
    acc.x *= cs; acc.y *= cs; acc.z *= cs; acc.w *= cs;
    float4 acc2 = make_float4(0.f, 0.f, 0.f, 0.f);
    int j = start;
    for (; j + 2 <= end; j += 2) {
        int s0 = g_csr[j], s1 = g_csr[j + 1];
        float c0 = g_dinv[s0] * di, c1 = g_dinv[s1] * di;
        float4 v0 = *(const float4*)(t + (size_t)s0 * DD + lane * 4);
        float4 v1 = *(const float4*)(t + (size_t)s1 * DD + lane * 4);
        acc.x = fmaf(c0, v0.x, acc.x);  acc.y = fmaf(c0, v0.y, acc.y);
        acc.z = fmaf(c0, v0.z, acc.z);  acc.w = fmaf(c0, v0.w, acc.w);
        acc2.x = fmaf(c1, v1.x, acc2.x); acc2.y = fmaf(c1, v1.y, acc2.y);
        acc2.z = fmaf(c1, v1.z, acc2.z); acc2.w = fmaf(c1, v1.w, acc2.w);
    }
    if (j < end) {
        int s = g_csr[j];
        float cc = g_dinv[s] * di;
        float4 v = *(const float4*)(t + (size_t)s * DD + lane * 4);
        acc.x = fmaf(cc, v.x, acc.x); acc.y = fmaf(cc, v.y, acc.y);
        acc.z = fmaf(cc, v.z, acc.z); acc.w = fmaf(cc, v.w, acc.w);
    }
    acc.x += acc2.x; acc.y += acc2.y; acc.z += acc2.z; acc.w += acc2.w;
    float4 b = ((const float4*)bias)[lane];
    acc.x = fmaxf(acc.x + b.x, 0.f); acc.y = fmaxf(acc.y + b.y, 0.f);
    acc.z = fmaxf(acc.z + b.z, 0.f); acc.w = fmaxf(acc.w + b.w, 0.f);
    size_t base = (size_t)w * DD + lane * 4;
    *(float4*)(out + base) = acc;
    bf162 h0, l0, h1, l1;
    split2(acc.x, acc.y, h0, l0);
    split2(acc.z, acc.w, h1, l1);
    *(bf162*)&oh[base] = h0; *(bf162*)&oh[base + 2] = h1;
    *(bf162*)&ol[base] = l0; *(bf162*)&ol[base + 2] = l1;
}

// SAGE mean aggregation -> split only
__global__ void k_sage_mean(const float* __restrict__ h,
                            bf16* __restrict__ oh, bf16* __restrict__ ol) {
    int w = (blockIdx.x * blockDim.x + threadIdx.x) >> 5;
    int lane = threadIdx.x & 31;
    if (w >= NN) return;
    int start = g_rowptr[w], end = g_rowptr[w + 1];
    float4 acc = make_float4(0.f, 0.f, 0.f, 0.f);
    float4 acc2 = make_float4(0.f, 0.f, 0.f, 0.f);
    int j = start;
    for (; j + 2 <= end; j += 2) {
        int s0 = g_csr[j], s1 = g_csr[j + 1];
        float4 v0 = *(const float4*)(h + (size_t)s0 * DD + lane * 4);
        float4 v1 = *(const float4*)(h + (size_t)s1 * DD + lane * 4);
        acc.x += v0.x; acc.y += v0.y; acc.z += v0.z; acc.w += v0.w;
        acc2.x += v1.x; acc2.y += v1.y; acc2.z += v1.z; acc2.w += v1.w;
    }
    if (j < end) {
        int s = g_csr[j];
        float4 v = *(const float4*)(h + (size_t)s * DD + lane * 4);
        acc.x += v.x; acc.y += v.y; acc.z += v.z; acc.w += v.w;
    }
    float cc = g_sinv[w];
    acc.x = (acc.x + acc2.x) * cc; acc.y = (acc.y + acc2.y) * cc;
    acc.z = (acc.z + acc2.z) * cc; acc.w = (acc.w + acc2.w) * cc;
    size_t base = (size_t)w * DD + lane * 4;
    bf162 h0, l0, h1, l1;
    split2(acc.x, acc.y, h0, l0);
    split2(acc.z, acc.w, h1, l1);
    *(bf162*)&oh[base] = h0; *(bf162*)&oh[base + 2] = h1;
    *(bf162*)&ol[base] = l0; *(bf162*)&ol[base + 2] = l1;
}

__global__ void k_alpha(const float* __restrict__ t, const float* __restrict__ a_s,
                        const float* __restrict__ a_d) {
    int w = (blockIdx.x * blockDim.x + threadIdx.x) >> 5;
    int lane = threadIdx.x & 31;
    if (w >= NN) return;
    float4 tv = *(const float4*)(t + (size_t)w * DD + lane * 4);
    float4 sv = *(const float4*)(a_s + lane * 4);
    float4 dv = *(const float4*)(a_d + lane * 4);
    float ss = tv.x * sv.x + tv.y * sv.y + tv.z * sv.z + tv.w * sv.w;
    float dd = tv.x * dv.x + tv.y * dv.y + tv.z * dv.z + tv.w * dv.w;
#pragma unroll
    for (int off = 16; off > 0; off >>= 1) {
        ss += __shfl_down_sync(0xffffffffu, ss, off);
        dd += __shfl_down_sync(0xffffffffu, dd, off);
    }
    if (lane == 0) { g_as[w] = ss; g_ad[w] = dd; }
}

// GAT -> split only
__global__ void k_gat(const float* __restrict__ h,
                      bf16* __restrict__ oh, bf16* __restrict__ ol,
                      const float* __restrict__ bias) {
    int w = (blockIdx.x * blockDim.x + threadIdx.x) >> 5;
    int lane = threadIdx.x & 31;
    if (w >= NN) return;
    float ad_d = g_ad[w];
    float as_d = g_as[w];
    int start = g_rowptr[w], end = g_rowptr[w + 1];

    const float NEG = -1e30f;
    float m_l = NEG, s_l = 0.f;
    for (int j = start + lane; j < end; j += 32) {
        int s = g_csr[j];
        float e = leaky(g_as[s] + ad_d);
        if (e > m_l) { s_l *= __expf(m_l - e); m_l = e; }
        s_l += __expf(e - m_l);
    }
#pragma unroll
    for (int off = 16; off > 0; off >>= 1) {
        float m_o = __shfl_xor_sync(0xffffffffu, m_l, off);
        float s_o = __shfl_xor_sync(0xffffffffu, s_l, off);
        float m_n = fmaxf(m_l, m_o);
        s_l = s_l * __expf(m_l - m_n) + s_o * __expf(m_o - m_n);
        m_l = m_n;
    }
    float e_self = leaky(as_d + ad_d);
    float m = fmaxf(m_l, e_self);
    float den = s_l * __expf(m_l - m) + __expf(e_self - m);
    float inv_den = 1.0f / den;

    float wself = __expf(e_self - m) * inv_den;
    float4 acc = *(const float4*)(h + (size_t)w * DD + lane * 4);
    acc.x *= wself; acc.y *= wself; acc.z *= wself; acc.w *= wself;
    float4 acc2 = make_float4(0.f, 0.f, 0.f, 0.f);
    int j = start;
    for (; j + 2 <= end; j += 2) {
        int s0 = g_csr[j], s1 = g_csr[j + 1];
        float w0 = __expf(leaky(g_as[s0] + ad_d) - m) * inv_den;
        float w1 = __expf(leaky(g_as[s1] + ad_d) - m) * inv_den;
        float4 v0 = *(const float4*)(h + (size_t)s0 * DD + lane * 4);
        float4 v1 = *(const float4*)(h + (size_t)s1 * DD + lane * 4);
        acc.x = fmaf(w0, v0.x, acc.x);  acc.y = fmaf(w0, v0.y, acc.y);
        acc.z = fmaf(w0, v0.z, acc.z);  acc.w = fmaf(w0, v0.w, acc.w);
        acc2.x = fmaf(w1, v1.x, acc2.x); acc2.y = fmaf(w1, v1.y, acc2.y);
        acc2.z = fmaf(w1, v1.z, acc2.z); acc2.w = fmaf(w1, v1.w, acc2.w);
    }
    if (j < end) {
        int s = g_csr[j];
        float wgt = __expf(leaky(g_as[s] + ad_d) - m) * inv_den;
        float4 v = *(const float4*)(h + (size_t)s * DD + lane * 4);
        acc.x = fmaf(wgt, v.x, acc.x); acc.y = fmaf(wgt, v.y, acc.y);
        acc.z = fmaf(wgt, v.z, acc.z); acc.w = fmaf(wgt, v.w, acc.w);
    }
    acc.x += acc2.x; acc.y += acc2.y; acc.z += acc2.z; acc.w += acc2.w;
    float4 b = ((const float4*)bias)[lane];
    acc.x = fmaxf(acc.x + b.x, 0.f); acc.y = fmaxf(acc.y + b.y, 0.f);
    acc.z = fmaxf(acc.z + b.z, 0.f); acc.w = fmaxf(acc.w + b.w, 0.f);
    size_t base = (size_t)w * DD + lane * 4;
    bf162 h0, l0, h1, l1;
    split2(acc.x, acc.y, h0, l0);
    split2(acc.z, acc.w, h1, l1);
    *(bf162*)&oh[base] = h0; *(bf162*)&oh[base + 2] = h1;
    *(bf162*)&ol[base] = l0; *(bf162*)&ol[base + 2] = l1;
}

__global__ void k_out_gather(const float* __restrict__ t, float* __restrict__ out,
                             const float* __restrict__ bias) {
    int w = (blockIdx.x * blockDim.x + threadIdx.x) >> 5;
    int lane = threadIdx.x & 31;
    if (w >= NN) return;
    float di = g_dinv[w];
    int start = g_rowptr[w], end = g_rowptr[w + 1];
    float2 acc = *(const float2*)(t + (size_t)w * OO + lane * 2);
    float cs = di * di;
    acc.x *= cs; acc.y *= cs;
    float2 acc2 = make_float2(0.f, 0.f);
    int j = start;
    for (; j + 2 <= end; j += 2) {
        int s0 = g_csr[j], s1 = g_csr[j + 1];
        float c0 = g_dinv[s0] * di, c1 = g_dinv[s1] * di;
        float2 v0 = *(const float2*)(t + (size_t)s0 * OO + lane * 2);
        float2 v1 = *(const float2*)(t + (size_t)s1 * OO + lane * 2);
        acc.x = fmaf(c0, v0.x, acc.x);   acc.y = fmaf(c0, v0.y, acc.y);
        acc2.x = fmaf(c1, v1.x, acc2.x); acc2.y = fmaf(c1, v1.y, acc2.y);
    }
    if (j < end) {
        int s = g_csr[j];
        float cc = g_dinv[s] * di;
        float2 v = *(const float2*)(t + (size_t)s * OO + lane * 2);
        acc.x = fmaf(cc, v.x, acc.x); acc.y = fmaf(cc, v.y, acc.y);
    }
    float2 b = ((const float2*)bias)[lane];
    acc.x += acc2.x + b.x; acc.y += acc2.y + b.y;
    *(float2*)(out + (size_t)w * OO + lane * 2) = acc;
}

// ---------------- launch ----------------
extern "C" void kernel_launch(void* const* d_in, const int* in_sizes, int n_in,
                              void* d_out, int out_size) {
    const float* x  = (const float*)d_in[0];
    const void*  ei = d_in[1];
    const float* W1 = (const float*)d_in[2];
    const float* b1 = (const float*)d_in[3];
    const float* Wl = (const float*)d_in[4];
    const float* Wr = (const float*)d_in[5];
    const float* bs = (const float*)d_in[6];
    const float* Wg = (const float*)d_in[7];
    const float* a_s = (const float*)d_in[8];
    const float* a_d = (const float*)d_in[9];
    const float* bg = (const float*)d_in[10];
    const float* Wo = (const float*)d_in[11];
    const float* bo = (const float*)d_in[12];
    float* out = (float*)d_out;

    float *p_t, *p_h, *p_agg; int* p_deg;
    bf16 *p0h, *p0l, *p1h, *p1l, *p2h, *p2l, *pwh, *pwl;
    cudaGetSymbolAddress((void**)&p_t, g_t);
    cudaGetSymbolAddress((void**)&p_h, g_h);
    cudaGetSymbolAddress((void**)&p_agg, g_agg);
    cudaGetSymbolAddress((void**)&p_deg, g_deg);
    cudaGetSymbolAddress((void**)&p0h, g_p0h);
    cudaGetSymbolAddress((void**)&p0l, g_p0l);
    cudaGetSymbolAddress((void**)&p1h, g_p1h);
    cudaGetSymbolAddress((void**)&p1l, g_p1l);
    cudaGetSymbolAddress((void**)&p2h, g_p2h);
    cudaGetSymbolAddress((void**)&p2l, g_p2l);
    cudaGetSymbolAddress((void**)&pwh, g_wh);
    cudaGetSymbolAddress((void**)&pwl, g_wl);

    const int TB = 256;
    const int bN   = (NN + TB - 1) / TB;
    const int bE   = NE / TB;
    const int bNW  = (NN * 32 + TB - 1) / TB;
    const int bW   = (128 * 128 + TB - 1) / TB;
    const int bWo  = (128 * 64 + TB - 1) / TB;
    const int bX4  = (NN * DD / 4 + TB - 1) / TB;
    const int gGemm = (NN + 127) / 128;

    // setup: degrees + CSR
    k_detect<<<1, 1>>>((const long long*)ei);
    k_zero_i<<<bN, TB>>>(p_deg, NN);
    k_deg<<<bE, TB>>>(ei);
    k_scal<<<bN, TB>>>();
    k_scan<<<1, 1024>>>();
    k_fill<<<bE, TB>>>(ei);

    // one-shot weight + x splitting
    k_convw<<<bW, TB>>>(W1, pwh + WOFF_W1, pwl + WOFF_W1, 128, 128);
    k_convw<<<bW, TB>>>(Wl, pwh + WOFF_WL, pwl + WOFF_WL, 128, 128);
    k_convw<<<bW, TB>>>(Wr, pwh + WOFF_WR, pwl + WOFF_WR, 128, 128);
    k_convw<<<bW, TB>>>(Wg, pwh + WOFF_WG, pwl + WOFF_WG, 128, 128);
    k_convw<<<bWo, TB>>>(Wo, pwh + WOFF_WO, pwl + WOFF_WO, 128, 64);
    k_split4<<<bX4, TB>>>(x, p0h, p0l, NN * DD / 4);

    // ---- layer 1: GCN + relu ----
    k_gemm_bf<128, false, false, false, false><<<gGemm, TB>>>(
        p0h, p0l, nullptr, nullptr, pwh + WOFF_W1, pwl + WOFF_W1, nullptr, nullptr,
        p_t, nullptr, nullptr, nullptr);
    k_gcn_gather<<<bNW, TB>>>(p_t, p_h, p1h, p1l, b1);   // h1 fp32 in g_h + split in P1

    // ---- layer 2: SAGE(mean) + relu ----
    k_sage_mean<<<bNW, TB>>>(p_h, p2h, p2l);             // agg split in P2
    k_gemm_bf<128, true, true, true, true><<<gGemm, TB>>>(
        p2h, p2l, p1h, p1l, pwh + WOFF_WL, pwl + WOFF_WL, pwh + WOFF_WR, pwl + WOFF_WR,
        nullptr, p0h, p0l, bs);                          // h2 split in P0

    // ---- layer 3: GAT + relu ----
    k_gemm_bf<128, false, false, false, false><<<gGemm, TB>>>(
        p0h, p0l, nullptr, nullptr, pwh + WOFF_WG, pwl + WOFF_WG, nullptr, nullptr,
        p_agg, nullptr, nullptr, nullptr);               // g fp32 in g_agg
    k_alpha<<<bNW, TB>>>(p_agg, a_s, a_d);
    k_gat<<<bNW, TB>>>(p_agg, p1h, p1l, bg);             // h3 split in P1

    // ---- layer 4: GCN output ----
    k_gemm_bf<64, false, false, false, false><<<gGemm, TB>>>(
        p1h, p1l, nullptr, nullptr, pwh + WOFF_WO, pwl + WOFF_WO, nullptr, nullptr,
        p_t, nullptr, nullptr, nullptr);
    k_out_gather<<<bNW, TB>>>(p_t, out, bo);
}